// round 4
// baseline (speedup 1.0000x reference)
#include <cuda_runtime.h>
#include <math.h>

// Problem shape (fixed by the dataset)
#define B_DIM 48
#define T_DIM 5000
#define F_DIM 161
#define BT (B_DIM * T_DIM)                  // 240000 rows
#define NEW_MAG_ELEMS ((size_t)BT * F_DIM)  // 38,640,000

#define CHUNK 100                   // frames per block
#define CHUNKS_PB (T_DIM / CHUNK)   // 50 chunks per batch
#define NBLK (B_DIM * CHUNKS_PB)    // 2400 blocks
#define THREADS 512
#define CHUNK_ELEMS (CHUNK * F_DIM) // 16100
#define CHUNK_F4 (CHUNK_ELEMS / 4)  // 4025 (exact)

// Dynamic smem: tile + sx + sA + sB (sinv overwrites sx)
#define SMEM_FLOATS (CHUNK_ELEMS + 3 * CHUNK)
#define SMEM_BYTES (SMEM_FLOATS * 4)

// Scratch (no cudaMalloc): carry chain + ordering counter
__device__ float    g_carry[NBLK];
__device__ int      g_flag[NBLK];
__device__ unsigned g_counter;

__global__ void k_init() {
    int i = blockIdx.x * blockDim.x + threadIdx.x;
    if (i < NBLK) g_flag[i] = 0;
    if (i == 0) g_counter = 0u;
}

__global__ void __launch_bounds__(THREADS) k_fused(
    const float* __restrict__ mag,
    float* __restrict__ out,
    float* __restrict__ out_gain)
{
    extern __shared__ float smem[];
    float* tile = smem;                   // CHUNK_ELEMS
    float* sx   = smem + CHUNK_ELEMS;     // CHUNK  (reused as sinv later)
    float* sA   = sx + CHUNK;             // CHUNK
    float* sB   = sA + CHUNK;             // CHUNK
    __shared__ unsigned s_vid;
    __shared__ float s_carry;

    int tid = threadIdx.x;
    if (tid == 0) s_vid = atomicAdd(&g_counter, 1u);
    __syncthreads();
    unsigned vid = s_vid;
    int b = vid % B_DIM;                  // chunk-major issue order
    int c = vid / B_DIM;

    size_t row0 = (size_t)b * T_DIM + (size_t)c * CHUNK;
    const float* base = mag + row0 * F_DIM;

    // ---- load tile: global -> smem, flat float4, fully coalesced ----
    {
        const float4* m4 = (const float4*)base;
        float4* t4 = (float4*)tile;
        #pragma unroll 4
        for (int i = tid; i < CHUNK_F4; i += THREADS)
            t4[i] = m4[i];
    }
    __syncthreads();

    // ---- pass 1: per-row power from smem (warp per row) ----
    int wid = tid >> 5, lane = tid & 31;
    for (int r = wid; r < CHUNK; r += THREADS / 32) {
        const float* m = tile + r * F_DIM;
        float s = 0.0f;
        #pragma unroll
        for (int f = lane; f < F_DIM; f += 32) {
            float v = m[f];
            s = fmaf(v, v, s);
        }
        #pragma unroll
        for (int off = 16; off > 0; off >>= 1)
            s += __shfl_xor_sync(0xffffffffu, s, off);
        if (lane == 0) {
            float m0 = m[0];
            float mN = m[F_DIM - 1];
            float sp = (2.0f * s - m0 * m0 - mN * mN) * (1.0f / 320.0f);
            sx[r] = sqrtf(sp);
        }
    }
    __syncthreads();

    // ---- warp 0: local affine scan over CHUNK rows; publish carry ----
    if (wid == 0) {
        float cA = 1.0f, cB = 0.0f;
        int t_base = c * CHUNK;
        #pragma unroll
        for (int w = 0; w < CHUNK / 32 + 1; w++) {
            int r = w * 32 + lane;
            float A, Bv;
            if (r < CHUNK) {
                float xv = sx[r];
                if (t_base + r == 0) { A = 0.0f; Bv = xv; }
                else                 { A = 0.9f; Bv = 0.1f * xv; }
            } else { A = 1.0f; Bv = 0.0f; }

            #pragma unroll
            for (int off = 1; off < 32; off <<= 1) {
                float Ap = __shfl_up_sync(0xffffffffu, A, off);
                float Bp = __shfl_up_sync(0xffffffffu, Bv, off);
                if (lane >= off) { Bv = fmaf(A, Bp, Bv); A *= Ap; }
            }
            float Apre = A * cA;
            float Bpre = fmaf(A, cB, Bv);
            if (r < CHUNK) { sA[r] = Apre; sB[r] = Bpre; }
            cA = __shfl_sync(0xffffffffu, Apre, 31);
            cB = __shfl_sync(0xffffffffu, Bpre, 31);
        }

        if (lane == 0) {
            float carry_in = 0.0f;
            if (c > 0) {
                int pidx = b * CHUNKS_PB + c - 1;
                while (atomicAdd(&g_flag[pidx], 0) == 0) {}
                __threadfence();
                carry_in = g_carry[pidx];
            }
            int idx = b * CHUNKS_PB + c;
            float carry_out = fmaf(cA, carry_in, cB);  // full-chunk composition
            g_carry[idx] = carry_out;
            __threadfence();
            atomicExch(&g_flag[idx], 1);
            s_carry = carry_in;
        }
    }
    __syncthreads();
    float carry = s_carry;

    // ---- gains + reciprocals (sinv aliases sx) ----
    float* sinv = sx;
    float* og = out_gain + row0;
    if (tid < CHUNK) {
        float g = fmaf(sA[tid], carry, sB[tid]);
        og[tid] = g;
        sinv[tid] = 1.0f / (g + 0.001f);
    }
    __syncthreads();

    // ---- pass 2: new_mag = tile * inv, float4 stores, ONE div per float4 ----
    {
        const float4* t4 = (const float4*)tile;
        float4* o4 = (float4*)(out + row0 * F_DIM);
        #pragma unroll 2
        for (int i = tid; i < CHUNK_F4; i += THREADS) {
            float4 v = t4[i];
            unsigned e0 = (unsigned)i * 4u;
            unsigned r0 = e0 / F_DIM;            // const-div -> mulhi
            unsigned rem = e0 - r0 * F_DIM;
            float inv0 = sinv[r0];
            float inv1 = (rem > (unsigned)(F_DIM - 4)) ? sinv[r0 + 1] : inv0;
            float4 rr;
            rr.x = v.x * inv0;
            rr.y = v.y * ((rem + 1 < F_DIM) ? inv0 : inv1);
            rr.z = v.z * ((rem + 2 < F_DIM) ? inv0 : inv1);
            rr.w = v.w * ((rem + 3 < F_DIM) ? inv0 : inv1);
            o4[i] = rr;
        }
    }
}

// ---------------------------------------------------------------------------
extern "C" void kernel_launch(void* const* d_in, const int* in_sizes, int n_in,
                              void* d_out, int out_size) {
    const float* mag = (const float*)d_in[0];
    float* out = (float*)d_out;
    float* out_gain = out + NEW_MAG_ELEMS;

    cudaFuncSetAttribute(k_fused, cudaFuncAttributeMaxDynamicSharedMemorySize,
                         SMEM_BYTES);

    k_init<<<(NBLK + 255) / 256, 256>>>();
    k_fused<<<NBLK, THREADS, SMEM_BYTES>>>(mag, out, out_gain);
}